// round 1
// baseline (speedup 1.0000x reference)
#include <cuda_runtime.h>
#include <math.h>

#define BATCH 1280
#define EDIM  512
#define D2    1024
#define D6    3072
#define TQ    64
#define TA    32
#define TV    64
#define BN_EPS 1e-5f

// ---------------- scratch (device globals: no allocation allowed) ----------
__device__ float g_qm[BATCH * D2];     // masked mean of question embedding
__device__ float g_am[BATCH * D2];     // masked mean of answer embedding
__device__ float g_X [BATCH * D6];     // concat [q_proj | vq | a_proj | va]
__device__ float g_h [BATCH * EDIM];   // ELU(X @ Wc1 + bc1)
__device__ float g_sum  [EDIM];
__device__ float g_sumsq[EDIM];
__device__ float g_wc [EDIM];          // gamma/sigma * Wc2
__device__ float g_cst[1];             // folded BN/bias constant

// ---------------- kernel 1: zero BN stat accumulators ----------------------
__global__ void zero_stats_kernel() {
    int i = threadIdx.x;
    g_sum[i] = 0.f;
    g_sumsq[i] = 0.f;
}

// ---------------- kernel 2: fused sequence-mean reductions -----------------
// blockIdx.x = b, blockIdx.y = which tensor (0:Q masked, 1:Vq, 2:A masked, 3:Va)
// 256 threads, one float4 column (4 floats of D=1024) per thread.
__global__ void reduce_kernel(const float4* __restrict__ Q,
                              const float4* __restrict__ Vq,
                              const float4* __restrict__ A,
                              const float4* __restrict__ Va,
                              const int* __restrict__ qlen,
                              const int* __restrict__ alen) {
    const int b = blockIdx.x;
    const int which = blockIdx.y;
    const int d4 = threadIdx.x;              // 0..255
    const int stride = BATCH * (D2 / 4);     // float4 stride between t slices

    const float4* p;
    int L;
    if (which == 0)      { L = max(qlen[b], 1); p = Q  + b * (D2 / 4) + d4; }
    else if (which == 1) { L = TV;              p = Vq + b * (D2 / 4) + d4; }
    else if (which == 2) { L = max(alen[b], 1); p = A  + b * (D2 / 4) + d4; }
    else                 { L = TV;              p = Va + b * (D2 / 4) + d4; }

    float4 acc = make_float4(0.f, 0.f, 0.f, 0.f);
    #pragma unroll 8
    for (int t = 0; t < L; t++) {
        float4 v = p[t * stride];
        acc.x += v.x; acc.y += v.y; acc.z += v.z; acc.w += v.w;
    }
    float inv = 1.f / (float)L;
    acc.x *= inv; acc.y *= inv; acc.z *= inv; acc.w *= inv;

    float4* dst;
    if (which == 0)      dst = (float4*)g_qm + b * (D2 / 4) + d4;
    else if (which == 1) dst = (float4*)g_X  + b * (D6 / 4) + (EDIM / 4) + d4;       // cols [512,1536)
    else if (which == 2) dst = (float4*)g_am + b * (D2 / 4) + d4;
    else                 dst = (float4*)g_X  + b * (D6 / 4) + (2048 / 4) + d4;       // cols [2048,3072)
    *dst = acc;
}

// ---------------- kernel 3/4/5: SIMT fp32 GEMM, 64x64 tile, 4x4/thread -----
// MODE 0: g_qm[1280,1024] @ Wq -> g_X cols [0,512)
// MODE 1: g_am[1280,1024] @ Wa -> g_X cols [1536,2048)
// MODE 2: g_X [1280,3072] @ Wc1 + ELU -> g_h
template <int MODE>
__global__ void sgemm_kernel(const float* __restrict__ W,
                             const float* __restrict__ bias) {
    const float* __restrict__ Aptr;
    float* __restrict__ C;
    int lda, ldc, K;
    if (MODE == 0)      { Aptr = g_qm; C = g_X;          lda = D2; ldc = D6;   K = D2; }
    else if (MODE == 1) { Aptr = g_am; C = g_X + 3 * EDIM; lda = D2; ldc = D6; K = D2; }
    else                { Aptr = g_X;  C = g_h;          lda = D6; ldc = EDIM; K = D6; }

    __shared__ __align__(16) float As[16 * 64];  // transposed: As[k][m]
    __shared__ __align__(16) float Bs[16 * 64];  // Bs[k][n]

    const int tid = threadIdx.x;                 // 256 threads
    const int tx = tid & 15, ty = tid >> 4;
    const int bm = blockIdx.y * 64, bn = blockIdx.x * 64;

    const int arow = tid >> 2;                   // 0..63
    const int ak   = (tid & 3) << 2;             // 0,4,8,12
    const int brow = tid >> 4;                   // 0..15
    const int bcol = (tid & 15) << 2;            // 0..60

    const float* Ag = Aptr + (bm + arow) * lda + ak;
    const float* Wg = W + brow * EDIM + bn + bcol;

    float c[4][4] = {};

    for (int k0 = 0; k0 < K; k0 += 16) {
        float4 av = *(const float4*)(Ag + k0);
        float4 bv = *(const float4*)(Wg + k0 * EDIM);
        __syncthreads();
        As[(ak + 0) * 64 + arow] = av.x;
        As[(ak + 1) * 64 + arow] = av.y;
        As[(ak + 2) * 64 + arow] = av.z;
        As[(ak + 3) * 64 + arow] = av.w;
        *(float4*)(Bs + brow * 64 + bcol) = bv;
        __syncthreads();
        #pragma unroll
        for (int k = 0; k < 16; k++) {
            float4 a = *(const float4*)(As + k * 64 + ty * 4);
            float4 b = *(const float4*)(Bs + k * 64 + tx * 4);
            c[0][0] += a.x * b.x; c[0][1] += a.x * b.y; c[0][2] += a.x * b.z; c[0][3] += a.x * b.w;
            c[1][0] += a.y * b.x; c[1][1] += a.y * b.y; c[1][2] += a.y * b.z; c[1][3] += a.y * b.w;
            c[2][0] += a.z * b.x; c[2][1] += a.z * b.y; c[2][2] += a.z * b.z; c[2][3] += a.z * b.w;
            c[3][0] += a.w * b.x; c[3][1] += a.w * b.y; c[3][2] += a.w * b.z; c[3][3] += a.w * b.w;
        }
    }

    #pragma unroll
    for (int i = 0; i < 4; i++) {
        int row = bm + ty * 4 + i;
        #pragma unroll
        for (int j = 0; j < 4; j++) {
            int col = bn + tx * 4 + j;
            float v = c[i][j] + bias[col];
            if (MODE == 2) v = (v > 0.f) ? v : expm1f(v);
            C[row * ldc + col] = v;
        }
    }
}

// ---------------- kernel 6: BN batch stats (sum, sumsq per column) ---------
__global__ void bn_stats_kernel() {
    const int r0 = blockIdx.x * 64;              // 20 blocks x 64 rows
    for (int c = threadIdx.x; c < EDIM; c += blockDim.x) {
        float s = 0.f, s2 = 0.f;
        #pragma unroll 8
        for (int r = 0; r < 64; r++) {
            float v = g_h[(r0 + r) * EDIM + c];
            s += v; s2 += v * v;
        }
        atomicAdd(&g_sum[c], s);
        atomicAdd(&g_sumsq[c], s2);
    }
}

// ---------------- kernel 7: fold BN + Wc2 into per-column weight + const ---
__global__ void bn_finalize_kernel(const float* __restrict__ gamma,
                                   const float* __restrict__ beta,
                                   const float* __restrict__ Wc2,
                                   const float* __restrict__ bc2) {
    __shared__ float red[EDIM];
    const int c = threadIdx.x;                   // 512 threads
    const float invB = 1.f / (float)BATCH;
    float mu  = g_sum[c] * invB;
    float var = fmaxf(g_sumsq[c] * invB - mu * mu, 0.f);
    float s   = gamma[c] * rsqrtf(var + BN_EPS);
    float w2  = Wc2[c];
    g_wc[c]   = s * w2;
    red[c]    = (beta[c] - mu * s) * w2;
    __syncthreads();
    for (int off = EDIM / 2; off > 0; off >>= 1) {
        if (c < off) red[c] += red[c + off];
        __syncthreads();
    }
    if (c == 0) g_cst[0] = red[0] + bc2[0];
}

// ---------------- kernel 8: final GEMV out[b] = h[b,:].g_wc + const --------
__global__ void gemv_kernel(float* __restrict__ out) {
    const int warp = threadIdx.x >> 5;
    const int lane = threadIdx.x & 31;
    const int b = blockIdx.x * 8 + warp;         // 160 blocks x 8 warps
    const float* hr = g_h + b * EDIM;
    float s = 0.f;
    #pragma unroll
    for (int c = lane; c < EDIM; c += 32) s += hr[c] * g_wc[c];
    #pragma unroll
    for (int off = 16; off > 0; off >>= 1) s += __shfl_down_sync(0xffffffffu, s, off);
    if (lane == 0) out[b] = s + g_cst[0];
}

// ---------------- launcher -------------------------------------------------
extern "C" void kernel_launch(void* const* d_in, const int* in_sizes, int n_in,
                              void* d_out, int out_size) {
    const float* Q    = (const float*)d_in[0];
    const float* Vq   = (const float*)d_in[1];
    const float* Aa   = (const float*)d_in[2];
    const float* Va   = (const float*)d_in[3];
    const int*   qlen = (const int*)d_in[4];
    const int*   alen = (const int*)d_in[5];
    const float* Wq   = (const float*)d_in[6];
    const float* bq   = (const float*)d_in[7];
    const float* Wa   = (const float*)d_in[8];
    const float* ba   = (const float*)d_in[9];
    const float* Wc1  = (const float*)d_in[10];
    const float* bc1  = (const float*)d_in[11];
    const float* gam  = (const float*)d_in[12];
    const float* bet  = (const float*)d_in[13];
    const float* Wc2  = (const float*)d_in[14];
    const float* bc2  = (const float*)d_in[15];
    float* out = (float*)d_out;

    zero_stats_kernel<<<1, EDIM>>>();
    reduce_kernel<<<dim3(BATCH, 4), 256>>>((const float4*)Q, (const float4*)Vq,
                                           (const float4*)Aa, (const float4*)Va,
                                           qlen, alen);
    sgemm_kernel<0><<<dim3(EDIM / 64, BATCH / 64), 256>>>(Wq, bq);
    sgemm_kernel<1><<<dim3(EDIM / 64, BATCH / 64), 256>>>(Wa, ba);
    sgemm_kernel<2><<<dim3(EDIM / 64, BATCH / 64), 256>>>(Wc1, bc1);
    bn_stats_kernel<<<BATCH / 64, 256>>>();
    bn_finalize_kernel<<<1, EDIM>>>(gam, bet, Wc2, bc2);
    gemv_kernel<<<BATCH / 8, 256>>>(out);
}